// round 5
// baseline (speedup 1.0000x reference)
#include <cuda_runtime.h>
#include <cstdint>

#define MM_    3844
#define CIN_   128
#define COUT_  256
#define KTOT_  1152
#define BM_    128
#define BN_    128
#define BK_    16
#define NTHR_  256
#define NT_    72          // k tiles: 9 khw * 8 ci-chunks
#define ASTR   24          // A smem stride (floats), k-interleaved layout
#define BSTR   264         // B smem stride (floats), [k][n]

// dynamic smem layout (floats)
#define OFF_A0  0
#define OFF_A1  (BM_ * ASTR)                      // 3072
#define OFF_B0  (2 * BM_ * ASTR)                  // 6144
#define OFF_B1  (2 * BM_ * ASTR + BK_ * BSTR)     // 10368
#define OFF_BBS (2 * BM_ * ASTR + 2 * BK_ * BSTR) // 14592
#define SMEM_BYTES ((OFF_BBS + BN_) * 4)          // 58880

__device__ __forceinline__ uint32_t to_tf32(float x) {
    uint32_t r;
    asm("cvt.rna.tf32.f32 %0, %1;" : "=r"(r) : "f"(x));
    return r;
}

__device__ __forceinline__ void mma_tf32(float c[4],
                                         uint32_t a0, uint32_t a1, uint32_t a2, uint32_t a3,
                                         uint32_t b0, uint32_t b1) {
    asm volatile(
        "mma.sync.aligned.m16n8k8.row.col.f32.tf32.tf32.f32 "
        "{%0,%1,%2,%3}, {%4,%5,%6,%7}, {%8,%9}, {%0,%1,%2,%3};"
        : "+f"(c[0]), "+f"(c[1]), "+f"(c[2]), "+f"(c[3])
        : "r"(a0), "r"(a1), "r"(a2), "r"(a3), "r"(b0), "r"(b1));
}

__global__ void __launch_bounds__(NTHR_, 2)
conv_mma_kernel(const float* __restrict__ X, const float* __restrict__ W,
                const float* __restrict__ bias, const float* __restrict__ Werr,
                const float* __restrict__ Berr, float* __restrict__ out)
{
    extern __shared__ float smf[];
    uint32_t* const Asm[2] = {(uint32_t*)(smf + OFF_A0), (uint32_t*)(smf + OFF_A1)};
    uint32_t* const Bsm[2] = {(uint32_t*)(smf + OFF_B0), (uint32_t*)(smf + OFF_B1)};
    float* const bbs = smf + OFF_BBS;

    const int tid  = threadIdx.x;
    const int lane = tid & 31;
    const int wid  = tid >> 5;
    const int wm   = wid >> 1;        // 0..3 (M dir, 32 rows each)
    const int wn   = wid & 1;         // 0..1 (N dir, 64 cols each)
    const int g    = lane >> 2;       // 0..7
    const int tq   = lane & 3;        // 0..3

    const int b  = blockIdx.z;
    const int m0 = blockIdx.y * BM_;
    const int n0 = blockIdx.x * BN_;

    if (tid < BN_) bbs[tid] = bias[n0 + tid] * Berr[b * COUT_ + n0 + tid];

    // ---- A fill mapping: thread -> (row = tid&127, k8 = tid>>7), 8 floats/tile
    const int arow = tid & 127;
    const int ak8  = tid >> 7;
    const int agm  = m0 + arow;
    const bool a_ok = (agm < MM_);
    const int amc = a_ok ? agm : 0;
    const int aho = amc / 62, awo = amc - aho * 62;
    const float* Xp = X + (((size_t)b * 64 + aho) * 64 + awo) * CIN_ + ak8 * 8;

    // ---- B fill mapping: thread -> (k = tid>>5 + 8*it, col = lane*4), 2 float4/tile
    const int bk = tid >> 5;          // 0..7
    const float* Wp = W    + (size_t)bk * COUT_ + n0 + lane * 4;
    const float* Ep = Werr + (size_t)b * ((size_t)KTOT_ * COUT_)
                           + (size_t)bk * COUT_ + n0 + lane * 4;

    float acc[2][8][4];
    #pragma unroll
    for (int i = 0; i < 2; i++)
        #pragma unroll
        for (int j = 0; j < 8; j++)
            #pragma unroll
            for (int q = 0; q < 4; q++) acc[i][j][q] = 0.0f;

    float4 ra0, ra1;       // A stage (8 floats)
    float4 rw[2], re[2];   // B stage (k and k+8)

    auto load_regs = [&](int u) {
        const int khw = u >> 3, cc = u & 7;
        const int kh = khw / 3, kw = khw - 3 * kh;
        const int aoff = (kh * 64 + kw) * CIN_ + cc * BK_;
        if (a_ok) {
            ra0 = *(const float4*)(Xp + aoff);
            ra1 = *(const float4*)(Xp + aoff + 4);
        } else {
            ra0 = make_float4(0.f, 0.f, 0.f, 0.f);
            ra1 = ra0;
        }
        #pragma unroll
        for (int it = 0; it < 2; it++) {
            size_t goff = (size_t)(khw * CIN_ + cc * BK_ + it * 8) * COUT_;
            rw[it] = *(const float4*)(Wp + goff);
            re[it] = *(const float4*)(Ep + goff);
        }
    };
    auto sts_regs = [&](int s) {
        // A: k-interleaved within 8-block: store order [v0,v4,v1,v5] [v2,v6,v3,v7]
        uint32_t* An = Asm[s] + arow * ASTR + ak8 * 8;
        uint4 p0 = {to_tf32(ra0.x), to_tf32(ra1.x), to_tf32(ra0.y), to_tf32(ra1.y)};
        uint4 p1 = {to_tf32(ra0.z), to_tf32(ra1.z), to_tf32(ra0.w), to_tf32(ra1.w)};
        *(uint4*)(An + 0) = p0;
        *(uint4*)(An + 4) = p1;
        #pragma unroll
        for (int it = 0; it < 2; it++) {
            uint4 bv = {to_tf32(rw[it].x * re[it].x), to_tf32(rw[it].y * re[it].y),
                        to_tf32(rw[it].z * re[it].z), to_tf32(rw[it].w * re[it].w)};
            *(uint4*)&Bsm[s][(bk + it * 8) * BSTR + lane * 4] = bv;
        }
    };

    load_regs(0);
    sts_regs(0);
    __syncthreads();

    const int arow0 = wm * 32 + g;          // frag row base for this thread
    for (int t = 0; t < NT_; t++) {
        const int cur = t & 1;
        const bool hn = (t + 1 < NT_);
        if (hn) load_regs(t + 1);

        const uint32_t* Ab = Asm[cur];
        const uint32_t* Bb = Bsm[cur];
        #pragma unroll
        for (int k8 = 0; k8 < 2; k8++) {
            uint32_t af[2][4], bf[8][2];
            #pragma unroll
            for (int mt = 0; mt < 2; mt++) {
                const uint32_t* ap = Ab + (arow0 + mt * 16) * ASTR + k8 * 8 + 2 * tq;
                uint2 p0 = *(const uint2*)(ap);             // {a0, a2}
                uint2 p1 = *(const uint2*)(ap + 8 * ASTR);  // {a1, a3}
                af[mt][0] = p0.x; af[mt][2] = p0.y;
                af[mt][1] = p1.x; af[mt][3] = p1.y;
            }
            #pragma unroll
            for (int nt = 0; nt < 8; nt++) {
                int c = wn * 64 + nt * 8 + g;
                bf[nt][0] = Bb[(k8 * 8 + tq) * BSTR + c];
                bf[nt][1] = Bb[(k8 * 8 + 4 + tq) * BSTR + c];
            }
            #pragma unroll
            for (int mt = 0; mt < 2; mt++)
                #pragma unroll
                for (int nt = 0; nt < 8; nt++)
                    mma_tf32(acc[mt][nt], af[mt][0], af[mt][1], af[mt][2], af[mt][3],
                             bf[nt][0], bf[nt][1]);
        }

        if (hn) sts_regs((t + 1) & 1);
        __syncthreads();
    }

    // ---- Epilogue: acc + bias*Berr -> out
    #pragma unroll
    for (int mt = 0; mt < 2; mt++) {
        #pragma unroll
        for (int h = 0; h < 2; h++) {
            int rg = m0 + wm * 32 + mt * 16 + g + h * 8;
            if (rg < MM_) {
                float* op = out + ((size_t)b * MM_ + rg) * COUT_ + n0 + wn * 64 + tq * 2;
                #pragma unroll
                for (int nt = 0; nt < 8; nt++) {
                    float2 bb = *(const float2*)&bbs[wn * 64 + nt * 8 + tq * 2];
                    float2 v;
                    v.x = acc[mt][nt][2 * h + 0] + bb.x;
                    v.y = acc[mt][nt][2 * h + 1] + bb.y;
                    *(float2*)(op + nt * 8) = v;
                }
            }
        }
    }
}

extern "C" void kernel_launch(void* const* d_in, const int* in_sizes, int n_in,
                              void* d_out, int out_size)
{
    const float* X    = (const float*)d_in[0];
    const float* W    = (const float*)d_in[1];
    const float* bias = (const float*)d_in[2];
    const float* Werr = (const float*)d_in[3];
    const float* Berr = (const float*)d_in[4];
    float* out = (float*)d_out;

    cudaFuncSetAttribute(conv_mma_kernel,
                         cudaFuncAttributeMaxDynamicSharedMemorySize, SMEM_BYTES);
    dim3 grid(COUT_ / BN_, (MM_ + BM_ - 1) / BM_, 64);   // (2, 31, 64)
    conv_mma_kernel<<<grid, NTHR_, SMEM_BYTES>>>(X, W, bias, Werr, Berr, out);
}

// round 6
// speedup vs baseline: 1.0801x; 1.0801x over previous
#include <cuda_runtime.h>
#include <cstdint>

#define MM_    3844
#define CIN_   128
#define COUT_  256
#define KTOT_  1152
#define BM_    256
#define BN_    128
#define BK_    16
#define NTHR_  512
#define NT_    72          // k tiles: 9 khw * 8 ci-chunks
#define ASTR   24          // A smem stride (floats), k-interleaved layout
#define BSTR   264         // B smem stride (floats), [k][n]

// dynamic smem layout (floats)
#define OFF_A0  0
#define OFF_A1  (BM_ * ASTR)                      // 6144
#define OFF_B0  (2 * BM_ * ASTR)                  // 12288
#define OFF_B1  (2 * BM_ * ASTR + BK_ * BSTR)     // 16512
#define OFF_BBS (2 * BM_ * ASTR + 2 * BK_ * BSTR) // 20736
#define SMEM_BYTES ((OFF_BBS + BN_) * 4)          // 83456

__device__ __forceinline__ uint32_t to_tf32(float x) {
    uint32_t r;
    asm("cvt.rna.tf32.f32 %0, %1;" : "=r"(r) : "f"(x));
    return r;
}

__device__ __forceinline__ void mma_tf32(float c[4],
                                         uint32_t a0, uint32_t a1, uint32_t a2, uint32_t a3,
                                         uint32_t b0, uint32_t b1) {
    asm volatile(
        "mma.sync.aligned.m16n8k8.row.col.f32.tf32.tf32.f32 "
        "{%0,%1,%2,%3}, {%4,%5,%6,%7}, {%8,%9}, {%0,%1,%2,%3};"
        : "+f"(c[0]), "+f"(c[1]), "+f"(c[2]), "+f"(c[3])
        : "r"(a0), "r"(a1), "r"(a2), "r"(a3), "r"(b0), "r"(b1));
}

__global__ void __launch_bounds__(NTHR_, 1)
conv_mma_kernel(const float* __restrict__ X, const float* __restrict__ W,
                const float* __restrict__ bias, const float* __restrict__ Werr,
                const float* __restrict__ Berr, float* __restrict__ out)
{
    extern __shared__ float smf[];
    uint32_t* const Asm[2] = {(uint32_t*)(smf + OFF_A0), (uint32_t*)(smf + OFF_A1)};
    uint32_t* const Bsm[2] = {(uint32_t*)(smf + OFF_B0), (uint32_t*)(smf + OFF_B1)};
    float* const bbs = smf + OFF_BBS;

    const int tid  = threadIdx.x;
    const int lane = tid & 31;
    const int wid  = tid >> 5;        // 0..15
    const int wm   = wid >> 2;        // 0..3 (M dir, 64 rows each)
    const int wn   = wid & 3;         // 0..3 (N dir, 32 cols each)
    const int g    = lane >> 2;       // 0..7
    const int tq   = lane & 3;        // 0..3

    const int b  = blockIdx.z;
    const int m0 = blockIdx.y * BM_;
    const int n0 = blockIdx.x * BN_;

    if (tid < BN_) bbs[tid] = bias[n0 + tid] * Berr[b * COUT_ + n0 + tid];

    // ---- A fill mapping: thread -> (row = tid&255, k8 = tid>>8), 8 floats/tile
    const int arow = tid & 255;
    const int ak8  = tid >> 8;        // 0 or 1
    const int agm  = m0 + arow;
    const bool a_ok = (agm < MM_);
    const int amc = a_ok ? agm : 0;
    const int aho = amc / 62, awo = amc - aho * 62;
    const float* Xp = X + (((size_t)b * 64 + aho) * 64 + awo) * CIN_ + ak8 * 8;

    // ---- B fill mapping: thread -> (k = tid>>5, col = lane*4), 1 float4/tile
    const int bk = tid >> 5;          // 0..15
    const float* Wp = W    + (size_t)bk * COUT_ + n0 + lane * 4;
    const float* Ep = Werr + (size_t)b * ((size_t)KTOT_ * COUT_)
                           + (size_t)bk * COUT_ + n0 + lane * 4;

    float acc[4][4][4];
    #pragma unroll
    for (int i = 0; i < 4; i++)
        #pragma unroll
        for (int j = 0; j < 4; j++)
            #pragma unroll
            for (int q = 0; q < 4; q++) acc[i][j][q] = 0.0f;

    float4 ra0, ra1;       // A stage (8 floats)
    float4 rw, re;         // B stage (1 float4 each)

    auto load_regs = [&](int u) {
        const int khw = u >> 3, cc = u & 7;
        const int kh = khw / 3, kw = khw - 3 * kh;
        const int aoff = (kh * 64 + kw) * CIN_ + cc * BK_;
        if (a_ok) {
            ra0 = *(const float4*)(Xp + aoff);
            ra1 = *(const float4*)(Xp + aoff + 4);
        } else {
            ra0 = make_float4(0.f, 0.f, 0.f, 0.f);
            ra1 = ra0;
        }
        size_t goff = (size_t)(khw * CIN_ + cc * BK_) * COUT_;
        rw = *(const float4*)(Wp + goff);
        re = *(const float4*)(Ep + goff);
    };
    auto sts_regs = [&](int s) {
        // A: k-interleaved within 8-block: store order [v0,v4,v1,v5] [v2,v6,v3,v7]
        uint32_t* An = Asm[s] + arow * ASTR + ak8 * 8;
        uint4 p0 = {to_tf32(ra0.x), to_tf32(ra1.x), to_tf32(ra0.y), to_tf32(ra1.y)};
        uint4 p1 = {to_tf32(ra0.z), to_tf32(ra1.z), to_tf32(ra0.w), to_tf32(ra1.w)};
        *(uint4*)(An + 0) = p0;
        *(uint4*)(An + 4) = p1;
        uint4 bv = {to_tf32(rw.x * re.x), to_tf32(rw.y * re.y),
                    to_tf32(rw.z * re.z), to_tf32(rw.w * re.w)};
        *(uint4*)&Bsm[s][bk * BSTR + lane * 4] = bv;
    };

    load_regs(0);
    sts_regs(0);
    __syncthreads();

    const int arow0 = wm * 64 + g;          // frag row base for this thread
    for (int t = 0; t < NT_; t++) {
        const int cur = t & 1;
        const bool hn = (t + 1 < NT_);
        if (hn) load_regs(t + 1);

        const uint32_t* Ab = Asm[cur];
        const uint32_t* Bb = Bsm[cur];
        #pragma unroll
        for (int k8 = 0; k8 < 2; k8++) {
            uint32_t af[4][4], bf[4][2];
            #pragma unroll
            for (int mt = 0; mt < 4; mt++) {
                const uint32_t* ap = Ab + (arow0 + mt * 16) * ASTR + k8 * 8 + 2 * tq;
                uint2 p0 = *(const uint2*)(ap);             // {a0, a2}
                uint2 p1 = *(const uint2*)(ap + 8 * ASTR);  // {a1, a3}
                af[mt][0] = p0.x; af[mt][2] = p0.y;
                af[mt][1] = p1.x; af[mt][3] = p1.y;
            }
            #pragma unroll
            for (int nt = 0; nt < 4; nt++) {
                int c = wn * 32 + nt * 8 + g;
                bf[nt][0] = Bb[(k8 * 8 + tq) * BSTR + c];
                bf[nt][1] = Bb[(k8 * 8 + 4 + tq) * BSTR + c];
            }
            #pragma unroll
            for (int mt = 0; mt < 4; mt++)
                #pragma unroll
                for (int nt = 0; nt < 4; nt++)
                    mma_tf32(acc[mt][nt], af[mt][0], af[mt][1], af[mt][2], af[mt][3],
                             bf[nt][0], bf[nt][1]);
        }

        if (hn) sts_regs((t + 1) & 1);
        __syncthreads();
    }

    // ---- Epilogue: acc + bias*Berr -> out
    #pragma unroll
    for (int mt = 0; mt < 4; mt++) {
        #pragma unroll
        for (int h = 0; h < 2; h++) {
            int rg = m0 + wm * 64 + mt * 16 + g + h * 8;
            if (rg < MM_) {
                float* op = out + ((size_t)b * MM_ + rg) * COUT_ + n0 + wn * 32 + tq * 2;
                #pragma unroll
                for (int nt = 0; nt < 4; nt++) {
                    float2 bb = *(const float2*)&bbs[wn * 32 + nt * 8 + tq * 2];
                    float2 v;
                    v.x = acc[mt][nt][2 * h + 0] + bb.x;
                    v.y = acc[mt][nt][2 * h + 1] + bb.y;
                    *(float2*)(op + nt * 8) = v;
                }
            }
        }
    }
}

extern "C" void kernel_launch(void* const* d_in, const int* in_sizes, int n_in,
                              void* d_out, int out_size)
{
    const float* X    = (const float*)d_in[0];
    const float* W    = (const float*)d_in[1];
    const float* bias = (const float*)d_in[2];
    const float* Werr = (const float*)d_in[3];
    const float* Berr = (const float*)d_in[4];
    float* out = (float*)d_out;

    cudaFuncSetAttribute(conv_mma_kernel,
                         cudaFuncAttributeMaxDynamicSharedMemorySize, SMEM_BYTES);
    dim3 grid(COUT_ / BN_, (MM_ + BM_ - 1) / BM_, 64);   // (2, 16, 64)
    conv_mma_kernel<<<grid, NTHR_, SMEM_BYTES>>>(X, W, bias, Werr, Berr, out);
}